// round 10
// baseline (speedup 1.0000x reference)
#include <cuda_runtime.h>

// EMEncoder_21483426414987 — masked per-label means + overall masked mean.
// tarsent_state [8,512,512] f32, tar_func [8,512] i32,
// refsent_state [8,32,256,512] f32, ref_func [8,32,256] i32.
// Output flat f32 concat (total 812592 floats), masks as 1.0/0.0.
//
// R7: hot loop is 100% register-resident — predicated LDG + select-mask
// fma.rn.f32x2 into 5 packed register accumulators. No smem LDS/STS RMW
// chains (R4/R6's limiter), no branches. smem only for label staging and
// the one-shot epilogue combine.
// Equal blocks: tar = 8 tiles x 8 chunks (Wc=16, NS=16), ref = 256 tiles x
// 4 chunks (Wc=32, NS=8); every block = 32 sentences = 8 batches of 4.

#define H    512
#define HQ   128    // H/4 float4 per row
#define NLAB 5

#define OFF_TAR_AUG   0
#define OFF_TAR_AMSK  20480
#define OFF_REF_AUG   20520
#define OFF_REF_AMSK  675880
#define OFF_TAR_PAP   677160
#define OFF_TAR_PMSK  681256
#define OFF_REF_PAP   681264
#define OFF_REF_PMSK  812336

typedef unsigned long long u64;

__device__ __forceinline__ void f4add(float4& a, const float4& v) {
    a.x += v.x; a.y += v.y; a.z += v.z; a.w += v.w;
}

// Branch-free predicated vector load: returns zeros when f == 0.
__device__ __forceinline__ float4 ldg_pred(const float4* p, int f) {
    float4 v = make_float4(0.f, 0.f, 0.f, 0.f);
    asm("{ .reg .pred p0; setp.ne.s32 p0, %4, 0;\n\t"
        "  @p0 ld.global.nc.v4.f32 {%0,%1,%2,%3}, [%5]; }"
        : "+f"(v.x), "+f"(v.y), "+f"(v.z), "+f"(v.w)
        : "r"(f), "l"(p));
    return v;
}

__device__ __forceinline__ u64 pack2(float lo, float hi) {
    u64 r; asm("mov.b64 %0, {%1, %2};" : "=l"(r) : "f"(lo), "f"(hi)); return r;
}
__device__ __forceinline__ void unpack2(u64 v, float& lo, float& hi) {
    asm("mov.b64 {%0, %1}, %2;" : "=f"(lo), "=f"(hi) : "l"(v));
}
// mask = (f==l) ? {1.0f,1.0f} : {0,0}, as one selp.b64
__device__ __forceinline__ u64 selmask2(int f, int l) {
    u64 m;
    asm("{ .reg .pred p; setp.eq.s32 p, %1, %2;\n\t"
        "  selp.b64 %0, 0x3F8000003F800000, 0, p; }"
        : "=l"(m) : "r"(f), "r"(l));
    return m;
}
// acc = v * m + acc  (packed f32x2 — Blackwell FFMA2)
__device__ __forceinline__ void fma2(u64& acc, u64 v, u64 m) {
    asm("fma.rn.f32x2 %0, %1, %2, %0;" : "+l"(acc) : "l"(v), "l"(m));
}

__global__ __launch_bounds__(256, 7) void em_reduce_kernel(
    const float* __restrict__ tar_state, const int* __restrict__ tar_func,
    const float* __restrict__ ref_state, const int* __restrict__ ref_func,
    float* __restrict__ out)
{
    __shared__ float4       spart[NLAB * 256];  // epilogue combine only
    __shared__ unsigned int spack[128];         // packed labels: 4 per word
    __shared__ int          scnt[NLAB];

    const int bid = blockIdx.x;
    const float4* state;
    const int*    func;
    int S, chunk, wsh;
    long aug_off, pap_off;
    int  amsk_off, pmsk_off;

    if (bid < 64) {                       // tar: 8 tiles x 8 chunks (Wc=16)
        const int b = bid >> 3;
        chunk    = bid & 7;
        wsh      = 4;
        S        = 512;
        state    = (const float4*)(tar_state + (size_t)b * 512 * H);
        func     = tar_func + b * 512;
        aug_off  = OFF_TAR_AUG + (long)b * NLAB * H;
        amsk_off = OFF_TAR_AMSK + b * NLAB;
        pap_off  = OFF_TAR_PAP + (long)b * H;
        pmsk_off = OFF_TAR_PMSK + b;
    } else {                              // ref: 256 tiles x 4 chunks (Wc=32)
        const int r   = bid - 64;
        const int idx = r >> 2;           // b*32 + d
        chunk    = r & 3;
        wsh      = 5;
        S        = 256;
        state    = (const float4*)(ref_state + (size_t)idx * 256 * H);
        func     = ref_func + idx * 256;
        aug_off  = OFF_REF_AUG + (long)idx * NLAB * H;
        amsk_off = OFF_REF_AMSK + idx * NLAB;
        pap_off  = OFF_REF_PAP + (long)idx * H;
        pmsk_off = OFF_REF_PMSK + idx;
    }

    const int tid    = threadIdx.x;
    const int Wc     = 1 << wsh;          // subgroup width (cols)
    const int NS     = 256 >> wsh;        // #subgroups
    const int nshift = 8 - wsh;           // log2(NS)
    const int colw   = tid & (Wc - 1);
    const int sub    = tid >> wsh;
    const int hq     = chunk * Wc + colw; // global float4 column

    if (tid < NLAB) scnt[tid] = 0;
    if (tid < 128)  spack[tid] = 0;
    __syncthreads();

    // stage packed labels + cooperative counts
    {
        unsigned char* cSp = (unsigned char*)spack;
        int l1 = 0, l2 = 0, l3 = 0, l4 = 0, l5 = 0;
        for (int s = tid; s < S; s += 256) {
            int f = func[s];
            cSp[((s & (NS - 1)) << 5) + (s >> nshift)] = (unsigned char)f;
            l1 += (f == 1); l2 += (f == 2); l3 += (f == 3);
            l4 += (f == 4); l5 += (f == 5);
        }
        if (l1) atomicAdd(&scnt[0], l1);
        if (l2) atomicAdd(&scnt[1], l2);
        if (l3) atomicAdd(&scnt[2], l3);
        if (l4) atomicAdd(&scnt[3], l4);
        if (l5) atomicAdd(&scnt[4], l5);
    }
    __syncthreads();

    // ---- hot loop: pure registers, branch-free ----
    u64 acc[NLAB][2];
    #pragma unroll
    for (int l = 0; l < NLAB; l++) { acc[l][0] = 0ull; acc[l][1] = 0ull; }

    const size_t kstep = (size_t)NS * HQ;          // float4 stride per k
    #pragma unroll 2
    for (int b = 0; b < 8; b++) {
        const unsigned int w = spack[sub * 8 + b]; // 4 labels, one LDS
        const float4* pb = state + ((size_t)(sub + (b << 2) * NS) * HQ + hq);
        #pragma unroll
        for (int k = 0; k < 4; k++) {
            const int f = (w >> (8 * k)) & 0xff;
            float4 v = ldg_pred(pb + (size_t)k * kstep, f);
            u64 v01 = pack2(v.x, v.y);
            u64 v23 = pack2(v.z, v.w);
            #pragma unroll
            for (int l = 0; l < NLAB; l++) {
                u64 m = selmask2(f, l + 1);
                fma2(acc[l][0], v01, m);
                fma2(acc[l][1], v23, m);
            }
        }
    }

    // publish per-thread partials, one barrier
    #pragma unroll
    for (int l = 0; l < NLAB; l++) {
        float4 a;
        unpack2(acc[l][0], a.x, a.y);
        unpack2(acc[l][1], a.z, a.w);
        spart[l * 256 + tid] = a;
    }
    __syncthreads();

    // ---- epilogue: warp l reduces label l; warp 5 paper mean; masks ----
    const int wid  = tid >> 5;
    const int lane = tid & 31;
    float4* out4 = (float4*)out;
    const long aug4 = aug_off >> 2;
    const long pap4 = pap_off >> 2;
    const float4 z = make_float4(0.f, 0.f, 0.f, 0.f);

    if (wid < NLAB) {
        if (lane < Wc) {
            float4 ssum = z;
            for (int p = 0; p < NS; p++)
                f4add(ssum, spart[wid * 256 + p * Wc + lane]);
            const int cnt = scnt[wid];
            float4 r = z;
            if (cnt > 0) {
                float inv = 1.0f / (float)cnt;
                r = make_float4(ssum.x*inv, ssum.y*inv, ssum.z*inv, ssum.w*inv);
            }
            out4[aug4 + (long)wid * HQ + chunk * Wc + lane] = r;
        }
    } else if (wid == 5) {
        if (lane < Wc) {
            float4 ssum = z;
            for (int l = 0; l < NLAB; l++)
                for (int p = 0; p < NS; p++)
                    f4add(ssum, spart[l * 256 + p * Wc + lane]);
            const int ct = scnt[0] + scnt[1] + scnt[2] + scnt[3] + scnt[4];
            float4 r = z;
            if (ct > 0) {
                float inv = 1.0f / (float)ct;
                r = make_float4(ssum.x*inv, ssum.y*inv, ssum.z*inv, ssum.w*inv);
            }
            out4[pap4 + chunk * Wc + lane] = r;
        }
    } else if (wid == 6 && lane == 0 && chunk == 0) {
        const int c1 = scnt[0], c2 = scnt[1], c3 = scnt[2];
        const int c4 = scnt[3], c5 = scnt[4];
        out[amsk_off + 0] = (c1 > 0) ? 1.0f : 0.0f;
        out[amsk_off + 1] = (c2 > 0) ? 1.0f : 0.0f;
        out[amsk_off + 2] = (c3 > 0) ? 1.0f : 0.0f;
        out[amsk_off + 3] = (c4 > 0) ? 1.0f : 0.0f;
        out[amsk_off + 4] = (c5 > 0) ? 1.0f : 0.0f;
        out[pmsk_off] = ((c1 + c2 + c3 + c4 + c5) > 0) ? 1.0f : 0.0f;
    }
}

extern "C" void kernel_launch(void* const* d_in, const int* in_sizes, int n_in,
                              void* d_out, int out_size) {
    const float* tar_state = (const float*)d_in[0];
    const int*   tar_func  = (const int*)d_in[1];
    const float* ref_state = (const float*)d_in[2];
    const int*   ref_func  = (const int*)d_in[3];
    float* out = (float*)d_out;

    // 8 tar tiles x 8 chunks + 256 ref tiles x 4 chunks = 1088 equal blocks
    em_reduce_kernel<<<64 + 1024, 256>>>(tar_state, tar_func,
                                         ref_state, ref_func, out);
}

// round 11
// speedup vs baseline: 1.3682x; 1.3682x over previous
#include <cuda_runtime.h>

// EMEncoder_21483426414987 — masked per-label means + overall masked mean.
// tarsent_state [8,512,512] f32, tar_func [8,512] i32,
// refsent_state [8,32,256,512] f32, ref_func [8,32,256] i32.
// Output flat f32 concat (total 812592 floats), masks as 1.0/0.0.
//
// R8: discriminating experiment — hot loop is unconditional contiguous
// streaming (no pad-skip gaps, no predication) into 5 register accumulator
// pairs (packed add.rn.f32x2), label dispatch via subgroup-uniform if/else
// chain. No smem loads/stores in the hot loop beyond 1 packed-label LDS per
// 4 sentences. Epilogue offsets recomputed from bid to minimize live regs.
// Equal blocks: tar = 8 tiles x 8 chunks (Wc=16, NS=16), ref = 256 tiles x
// 4 chunks (Wc=32, NS=8); every block = 32 sentences.

#define H    512
#define HQ   128    // H/4 float4 per row
#define NLAB 5

#define OFF_TAR_AUG   0
#define OFF_TAR_AMSK  20480
#define OFF_REF_AUG   20520
#define OFF_REF_AMSK  675880
#define OFF_TAR_PAP   677160
#define OFF_TAR_PMSK  681256
#define OFF_REF_PAP   681264
#define OFF_REF_PMSK  812336

typedef unsigned long long u64;

__device__ __forceinline__ void f4add(float4& a, const float4& v) {
    a.x += v.x; a.y += v.y; a.z += v.z; a.w += v.w;
}

// 16B vector load as 2x u64 (keeps data packed for f32x2 adds)
__device__ __forceinline__ void ldg2(const float4* p, u64& x, u64& y) {
    asm("ld.global.nc.v2.u64 {%0,%1}, [%2];" : "=l"(x), "=l"(y) : "l"(p));
}
// a += v as packed f32x2 (Blackwell FFMA-pipe, 1 inst per 2 floats)
__device__ __forceinline__ void add2(u64& a, u64 v) {
    asm("add.rn.f32x2 %0, %0, %1;" : "+l"(a) : "l"(v));
}
__device__ __forceinline__ float4 unpack4(u64 lo, u64 hi) {
    float4 r;
    asm("mov.b64 {%0, %1}, %2;" : "=f"(r.x), "=f"(r.y) : "l"(lo));
    asm("mov.b64 {%0, %1}, %2;" : "=f"(r.z), "=f"(r.w) : "l"(hi));
    return r;
}

__global__ __launch_bounds__(256, 7) void em_reduce_kernel(
    const float* __restrict__ tar_state, const int* __restrict__ tar_func,
    const float* __restrict__ ref_state, const int* __restrict__ ref_func,
    float* __restrict__ out)
{
    __shared__ float4       spart[NLAB * 256];  // epilogue combine only
    __shared__ unsigned int spack[128];         // packed labels: 4 per word
    __shared__ int          scnt[NLAB];

    const int bid = blockIdx.x;
    const float4* state;
    const int*    func;
    int S, chunk, wsh;

    if (bid < 64) {                       // tar: 8 tiles x 8 chunks (Wc=16)
        const int b = bid >> 3;
        chunk = bid & 7;
        wsh   = 4;
        S     = 512;
        state = (const float4*)(tar_state + (size_t)b * 512 * H);
        func  = tar_func + b * 512;
    } else {                              // ref: 256 tiles x 4 chunks (Wc=32)
        const int r   = bid - 64;
        const int idx = r >> 2;           // b*32 + d
        chunk = r & 3;
        wsh   = 5;
        S     = 256;
        state = (const float4*)(ref_state + (size_t)idx * 256 * H);
        func  = ref_func + idx * 256;
    }

    const int tid    = threadIdx.x;
    const int Wc     = 1 << wsh;          // subgroup width (cols)
    const int NS     = 256 >> wsh;        // #subgroups
    const int nshift = 8 - wsh;           // log2(NS)
    const int colw   = tid & (Wc - 1);
    const int sub    = tid >> wsh;
    const int hq     = chunk * Wc + colw; // global float4 column

    if (tid < NLAB) scnt[tid] = 0;
    if (tid < 128)  spack[tid] = 0;
    __syncthreads();

    // stage packed labels + cooperative counts
    {
        unsigned char* cSp = (unsigned char*)spack;
        int l1 = 0, l2 = 0, l3 = 0, l4 = 0, l5 = 0;
        for (int s = tid; s < S; s += 256) {
            int f = func[s];
            cSp[((s & (NS - 1)) << 5) + (s >> nshift)] = (unsigned char)f;
            l1 += (f == 1); l2 += (f == 2); l3 += (f == 3);
            l4 += (f == 4); l5 += (f == 5);
        }
        if (l1) atomicAdd(&scnt[0], l1);
        if (l2) atomicAdd(&scnt[1], l2);
        if (l3) atomicAdd(&scnt[2], l3);
        if (l4) atomicAdd(&scnt[3], l4);
        if (l5) atomicAdd(&scnt[4], l5);
    }
    __syncthreads();

    // ---- hot loop: unconditional contiguous loads, register accumulators ----
    u64 a10=0, a11=0, a20=0, a21=0, a30=0, a31=0, a40=0, a41=0, a50=0, a51=0;
    const size_t  kstep = (size_t)NS * HQ;       // float4 stride per sentence-step
    const float4* p0    = state + (size_t)sub * HQ + hq;

    #pragma unroll
    for (int b = 0; b < 8; b++) {
        const unsigned int w = spack[sub * 8 + b];  // 4 labels, one LDS
        const float4* pb = p0 + (size_t)(b * 4) * kstep;
        #pragma unroll
        for (int k = 0; k < 4; k++) {
            u64 x, y;
            ldg2(pb + (size_t)k * kstep, x, y);
            const int f = (w >> (8 * k)) & 0xff;
            // subgroup-uniform branch; f==0 (pad) falls through
            if      (f == 1) { add2(a10, x); add2(a11, y); }
            else if (f == 2) { add2(a20, x); add2(a21, y); }
            else if (f == 3) { add2(a30, x); add2(a31, y); }
            else if (f == 4) { add2(a40, x); add2(a41, y); }
            else if (f == 5) { add2(a50, x); add2(a51, y); }
        }
    }

    // publish per-thread partials, one barrier
    spart[0 * 256 + tid] = unpack4(a10, a11);
    spart[1 * 256 + tid] = unpack4(a20, a21);
    spart[2 * 256 + tid] = unpack4(a30, a31);
    spart[3 * 256 + tid] = unpack4(a40, a41);
    spart[4 * 256 + tid] = unpack4(a50, a51);
    __syncthreads();

    // ---- epilogue (offsets recomputed from bid) ----
    long aug_off, pap_off;
    int  amsk_off, pmsk_off;
    if (bid < 64) {
        const int b = bid >> 3;
        aug_off  = OFF_TAR_AUG + (long)b * NLAB * H;
        amsk_off = OFF_TAR_AMSK + b * NLAB;
        pap_off  = OFF_TAR_PAP + (long)b * H;
        pmsk_off = OFF_TAR_PMSK + b;
    } else {
        const int idx = (bid - 64) >> 2;
        aug_off  = OFF_REF_AUG + (long)idx * NLAB * H;
        amsk_off = OFF_REF_AMSK + idx * NLAB;
        pap_off  = OFF_REF_PAP + (long)idx * H;
        pmsk_off = OFF_REF_PMSK + idx;
    }

    const int wid  = tid >> 5;
    const int lane = tid & 31;
    float4* out4 = (float4*)out;
    const long aug4 = aug_off >> 2;
    const long pap4 = pap_off >> 2;
    const float4 z = make_float4(0.f, 0.f, 0.f, 0.f);

    if (wid < NLAB) {
        if (lane < Wc) {
            float4 ssum = z;
            for (int p = 0; p < NS; p++)
                f4add(ssum, spart[wid * 256 + p * Wc + lane]);
            const int cnt = scnt[wid];
            float4 r = z;
            if (cnt > 0) {
                float inv = 1.0f / (float)cnt;
                r = make_float4(ssum.x*inv, ssum.y*inv, ssum.z*inv, ssum.w*inv);
            }
            out4[aug4 + (long)wid * HQ + chunk * Wc + lane] = r;
        }
    } else if (wid == 5) {
        if (lane < Wc) {
            float4 ssum = z;
            for (int l = 0; l < NLAB; l++)
                for (int p = 0; p < NS; p++)
                    f4add(ssum, spart[l * 256 + p * Wc + lane]);
            const int ct = scnt[0] + scnt[1] + scnt[2] + scnt[3] + scnt[4];
            float4 r = z;
            if (ct > 0) {
                float inv = 1.0f / (float)ct;
                r = make_float4(ssum.x*inv, ssum.y*inv, ssum.z*inv, ssum.w*inv);
            }
            out4[pap4 + chunk * Wc + lane] = r;
        }
    } else if (wid == 6 && lane == 0 && chunk == 0) {
        const int c1 = scnt[0], c2 = scnt[1], c3 = scnt[2];
        const int c4 = scnt[3], c5 = scnt[4];
        out[amsk_off + 0] = (c1 > 0) ? 1.0f : 0.0f;
        out[amsk_off + 1] = (c2 > 0) ? 1.0f : 0.0f;
        out[amsk_off + 2] = (c3 > 0) ? 1.0f : 0.0f;
        out[amsk_off + 3] = (c4 > 0) ? 1.0f : 0.0f;
        out[amsk_off + 4] = (c5 > 0) ? 1.0f : 0.0f;
        out[pmsk_off] = ((c1 + c2 + c3 + c4 + c5) > 0) ? 1.0f : 0.0f;
    }
}

extern "C" void kernel_launch(void* const* d_in, const int* in_sizes, int n_in,
                              void* d_out, int out_size) {
    const float* tar_state = (const float*)d_in[0];
    const int*   tar_func  = (const int*)d_in[1];
    const float* ref_state = (const float*)d_in[2];
    const int*   ref_func  = (const int*)d_in[3];
    float* out = (float*)d_out;

    // 8 tar tiles x 8 chunks + 256 ref tiles x 4 chunks = 1088 equal blocks
    em_reduce_kernel<<<64 + 1024, 256>>>(tar_state, tar_func,
                                         ref_state, ref_func, out);
}

// round 12
// speedup vs baseline: 1.6338x; 1.1941x over previous
#include <cuda_runtime.h>

// EMEncoder_21483426414987 — masked per-label means + overall masked mean.
// tarsent_state [8,512,512] f32, tar_func [8,512] i32,
// refsent_state [8,32,256,512] f32, ref_func [8,32,256] i32.
// Output flat f32 concat (total 812592 floats), masks as 1.0/0.0.
//
// R9: cp.async 4-stage pipeline. Loads go gmem->smem via cp.async.cg (no
// dest registers -> MLP no longer register-capped, the R4..R8 limiter).
// Each thread self-produces/self-consumes its own 16B slot: per-thread
// wait_group ordering only, ZERO barriers in the hot loop. Pad rows (f==0)
// skipped at issue (predicated cp.async); stale smem never accumulated.
// Register accumulators (packed add.rn.f32x2), subgroup-uniform label branch.
// Equal blocks: tar = 8 tiles x 8 chunks (Wc=16, NS=16), ref = 256 tiles x
// 4 chunks (Wc=32, NS=8); every block = 32 stages of 4KB.

#define H    512
#define HQ   128    // H/4 float4 per row
#define NLAB 5
#define NSTG 4      // pipeline stages (ring)

#define OFF_TAR_AUG   0
#define OFF_TAR_AMSK  20480
#define OFF_REF_AUG   20520
#define OFF_REF_AMSK  675880
#define OFF_TAR_PAP   677160
#define OFF_TAR_PMSK  681256
#define OFF_REF_PAP   681264
#define OFF_REF_PMSK  812336

typedef unsigned long long u64;

__device__ __forceinline__ void f4add(float4& a, const float4& v) {
    a.x += v.x; a.y += v.y; a.z += v.z; a.w += v.w;
}
__device__ __forceinline__ void add2(u64& a, u64 v) {
    asm("add.rn.f32x2 %0, %0, %1;" : "+l"(a) : "l"(v));
}
__device__ __forceinline__ float4 unpack4(u64 lo, u64 hi) {
    float4 r;
    asm("mov.b64 {%0, %1}, %2;" : "=f"(r.x), "=f"(r.y) : "l"(lo));
    asm("mov.b64 {%0, %1}, %2;" : "=f"(r.z), "=f"(r.w) : "l"(hi));
    return r;
}
// predicated 16B async copy gmem->smem (skipped when cond == 0)
__device__ __forceinline__ void cp16_pred(unsigned int saddr, const void* g, int cond) {
    asm volatile("{ .reg .pred p; setp.ne.s32 p, %2, 0;\n\t"
                 "@p cp.async.cg.shared.global [%0], [%1], 16; }"
                 :: "r"(saddr), "l"(g), "r"(cond));
}
__device__ __forceinline__ void cp_commit() {
    asm volatile("cp.async.commit_group;" ::: "memory");
}
__device__ __forceinline__ void cp_wait3() {
    asm volatile("cp.async.wait_group 3;" ::: "memory");
}
// 16B smem load as 2x u64
__device__ __forceinline__ void lds2(unsigned int saddr, u64& x, u64& y) {
    asm volatile("ld.shared.v2.u64 {%0,%1}, [%2];" : "=l"(x), "=l"(y) : "r"(saddr));
}

__global__ __launch_bounds__(256, 7) void em_reduce_kernel(
    const float* __restrict__ tar_state, const int* __restrict__ tar_func,
    const float* __restrict__ ref_state, const int* __restrict__ ref_func,
    float* __restrict__ out)
{
    // union: first NSTG*256 entries = pipeline ring (16KB); whole = spart (20KB)
    __shared__ float4        shmem[NLAB * 256];
    __shared__ unsigned char slab[544];       // labels, byte [sub*32 + k], padded
    __shared__ int           scnt[NLAB];

    const int bid = blockIdx.x;
    const float4* state;
    const int*    func;
    int S, chunk, wsh;

    if (bid < 64) {                       // tar: 8 tiles x 8 chunks (Wc=16)
        const int b = bid >> 3;
        chunk = bid & 7;
        wsh   = 4;
        S     = 512;
        state = (const float4*)(tar_state + (size_t)b * 512 * H);
        func  = tar_func + b * 512;
    } else {                              // ref: 256 tiles x 4 chunks (Wc=32)
        const int r   = bid - 64;
        const int idx = r >> 2;           // b*32 + d
        chunk = r & 3;
        wsh   = 5;
        S     = 256;
        state = (const float4*)(ref_state + (size_t)idx * 256 * H);
        func  = ref_func + idx * 256;
    }

    const int tid    = threadIdx.x;
    const int Wc     = 1 << wsh;          // subgroup width (cols)
    const int NS     = 256 >> wsh;        // #subgroups
    const int nshift = 8 - wsh;           // log2(NS)
    const int colw   = tid & (Wc - 1);
    const int sub    = tid >> wsh;
    const int hq     = chunk * Wc + colw; // global float4 column

    if (tid < NLAB) scnt[tid] = 0;
    if (tid < 32) { ((unsigned int*)slab)[128 + tid % 8] = 0; }  // pad words
    __syncthreads();

    // stage labels (byte layout: sub*32 + k) + cooperative counts
    {
        int l1 = 0, l2 = 0, l3 = 0, l4 = 0, l5 = 0;
        for (int s = tid; s < S; s += 256) {
            int f = func[s];
            slab[((s & (NS - 1)) << 5) + (s >> nshift)] = (unsigned char)f;
            l1 += (f == 1); l2 += (f == 2); l3 += (f == 3);
            l4 += (f == 4); l5 += (f == 5);
        }
        if (l1) atomicAdd(&scnt[0], l1);
        if (l2) atomicAdd(&scnt[1], l2);
        if (l3) atomicAdd(&scnt[2], l3);
        if (l4) atomicAdd(&scnt[3], l4);
        if (l5) atomicAdd(&scnt[4], l5);
    }
    __syncthreads();

    // ---- cp.async pipelined hot loop ----
    u64 a10=0, a11=0, a20=0, a21=0, a30=0, a31=0, a40=0, a41=0, a50=0, a51=0;
    const size_t  kstep = (size_t)NS * HQ;           // float4 per stage step
    const float4* pg    = state + (size_t)sub * HQ + hq;
    const unsigned int sbase =
        (unsigned int)__cvta_generic_to_shared(shmem) + (unsigned int)tid * 16u;
    const int lbase = sub * 32;

    // prologue: issue stages 0..2
    #pragma unroll
    for (int k = 0; k < NSTG - 1; k++) {
        const int f = slab[lbase + k];
        cp16_pred(sbase + (unsigned int)k * 4096u, pg, f);
        cp_commit();
        pg += kstep;
    }

    // main: issue stage k+3 (predicated, empty-commit past end), consume k
    #pragma unroll 4
    for (int k = 0; k < 32; k++) {
        const int fn   = slab[lbase + k + 3];        // padded slab: safe
        const int cond = (k < 29) ? fn : 0;
        cp16_pred(sbase + (unsigned int)((k + 3) & 3) * 4096u, pg, cond);
        cp_commit();
        pg += kstep;

        cp_wait3();                                  // stage k complete
        u64 x, y;
        lds2(sbase + (unsigned int)(k & 3) * 4096u, x, y);
        const int f = slab[lbase + k];
        // subgroup-uniform branch; f==0 (pad) falls through (slot stale, unused)
        if      (f == 1) { add2(a10, x); add2(a11, y); }
        else if (f == 2) { add2(a20, x); add2(a21, y); }
        else if (f == 3) { add2(a30, x); add2(a31, y); }
        else if (f == 4) { add2(a40, x); add2(a41, y); }
        else if (f == 5) { add2(a50, x); add2(a51, y); }
    }

    __syncthreads();                    // all consumption done; reuse ring as spart

    shmem[0 * 256 + tid] = unpack4(a10, a11);
    shmem[1 * 256 + tid] = unpack4(a20, a21);
    shmem[2 * 256 + tid] = unpack4(a30, a31);
    shmem[3 * 256 + tid] = unpack4(a40, a41);
    shmem[4 * 256 + tid] = unpack4(a50, a51);
    __syncthreads();

    // ---- epilogue (offsets recomputed from bid) ----
    long aug_off, pap_off;
    int  amsk_off, pmsk_off;
    if (bid < 64) {
        const int b = bid >> 3;
        aug_off  = OFF_TAR_AUG + (long)b * NLAB * H;
        amsk_off = OFF_TAR_AMSK + b * NLAB;
        pap_off  = OFF_TAR_PAP + (long)b * H;
        pmsk_off = OFF_TAR_PMSK + b;
    } else {
        const int idx = (bid - 64) >> 2;
        aug_off  = OFF_REF_AUG + (long)idx * NLAB * H;
        amsk_off = OFF_REF_AMSK + idx * NLAB;
        pap_off  = OFF_REF_PAP + (long)idx * H;
        pmsk_off = OFF_REF_PMSK + idx;
    }

    const int wid  = tid >> 5;
    const int lane = tid & 31;
    float4* out4 = (float4*)out;
    const long aug4 = aug_off >> 2;
    const long pap4 = pap_off >> 2;
    const float4 z = make_float4(0.f, 0.f, 0.f, 0.f);

    if (wid < NLAB) {
        if (lane < Wc) {
            float4 ssum = z;
            for (int p = 0; p < NS; p++)
                f4add(ssum, shmem[wid * 256 + p * Wc + lane]);
            const int cnt = scnt[wid];
            float4 r = z;
            if (cnt > 0) {
                float inv = 1.0f / (float)cnt;
                r = make_float4(ssum.x*inv, ssum.y*inv, ssum.z*inv, ssum.w*inv);
            }
            out4[aug4 + (long)wid * HQ + chunk * Wc + lane] = r;
        }
    } else if (wid == 5) {
        if (lane < Wc) {
            float4 ssum = z;
            for (int l = 0; l < NLAB; l++)
                for (int p = 0; p < NS; p++)
                    f4add(ssum, shmem[l * 256 + p * Wc + lane]);
            const int ct = scnt[0] + scnt[1] + scnt[2] + scnt[3] + scnt[4];
            float4 r = z;
            if (ct > 0) {
                float inv = 1.0f / (float)ct;
                r = make_float4(ssum.x*inv, ssum.y*inv, ssum.z*inv, ssum.w*inv);
            }
            out4[pap4 + chunk * Wc + lane] = r;
        }
    } else if (wid == 6 && lane == 0 && chunk == 0) {
        const int c1 = scnt[0], c2 = scnt[1], c3 = scnt[2];
        const int c4 = scnt[3], c5 = scnt[4];
        out[amsk_off + 0] = (c1 > 0) ? 1.0f : 0.0f;
        out[amsk_off + 1] = (c2 > 0) ? 1.0f : 0.0f;
        out[amsk_off + 2] = (c3 > 0) ? 1.0f : 0.0f;
        out[amsk_off + 3] = (c4 > 0) ? 1.0f : 0.0f;
        out[amsk_off + 4] = (c5 > 0) ? 1.0f : 0.0f;
        out[pmsk_off] = ((c1 + c2 + c3 + c4 + c5) > 0) ? 1.0f : 0.0f;
    }
}

extern "C" void kernel_launch(void* const* d_in, const int* in_sizes, int n_in,
                              void* d_out, int out_size) {
    const float* tar_state = (const float*)d_in[0];
    const int*   tar_func  = (const int*)d_in[1];
    const float* ref_state = (const float*)d_in[2];
    const int*   ref_func  = (const int*)d_in[3];
    float* out = (float*)d_out;

    // 8 tar tiles x 8 chunks + 256 ref tiles x 4 chunks = 1088 equal blocks
    em_reduce_kernel<<<64 + 1024, 256>>>(tar_state, tar_func,
                                         ref_state, ref_func, out);
}